// round 3
// baseline (speedup 1.0000x reference)
#include <cuda_runtime.h>
#include <math.h>

#define B   16
#define CI  64
#define CO  64
#define H   256
#define W   256
#define MH  8
#define MW  12
#define S1  (1.0f/256.0f)
#define S2  (1.0f/256.0f)

// ---------- device scratch ----------
__device__ float d_ctab[MW*W];           // cos(2*pi*ky*w/256)  (for k45 synthesis regs)
__device__ float d_stab[MW*W];           // sin(2*pi*ky*w/256)
__device__ float d_hc[MH*H];             // cos(2*pi*kx*h/256)
__device__ float d_hs[MH*H];             // sin(2*pi*kx*h/256)
__device__ float d_twp[128*28];          // packed folded twiddles, pre-scaled by S1, sin pre-negated
__device__ float d_Xp[(size_t)B*96*CI*4*2];  // per-block partial X: [b][mode][ci][part4] float2
__device__ float d_Y[(size_t)B*CO*96*2];     // [b][o][mode][2]
__device__ float d_wT[(size_t)96*CI*CO*2];   // [mode][i][o][2]

// ---------- trig tables ----------
__global__ void init_trig() {
    int idx = blockIdx.x * blockDim.x + threadIdx.x;
    if (idx < 3072) {               // 12 ky x 256 w : k45 synthesis tables
        int ky = idx >> 8, w = idx & 255;
        double a = 2.0 * (double)ky * (double)w / 256.0;
        double s, c; sincospi(a, &s, &c);
        d_ctab[idx] = (float)c; d_stab[idx] = (float)s;
    } else if (idx < 5120) {        // 8 kx x 256 h
        int j = idx - 3072;
        int kx = j >> 8, h = j & 255;
        double a = 2.0 * (double)kx * (double)h / 256.0;
        double s, c; sincospi(a, &s, &c);
        d_hc[j] = (float)c; d_hs[j] = (float)s;
    } else if (idx < 5120 + 128*24) {  // folded fwd twiddles
        int j = idx - 5120;
        int w = j / 24, k = j % 24;     // w<128
        // slots: 0..5 cE (ky=2m), 6..11 sE, 12..17 cO (ky=2m+1), 18..23 sO
        int m = k % 6;
        int ky = (k < 12) ? 2*m : 2*m + 1;
        double a = 2.0 * (double)ky * (double)w / 256.0;
        double s, c; sincospi(a, &s, &c);
        bool is_sin = ((k >= 6 && k < 12) || k >= 18);
        d_twp[w*28 + k] = is_sin ? (float)(-S1 * s) : (float)(S1 * c);
    }
}

// ---------- weight transpose: [i][o][m][2] -> [m][i][o][2] ----------
__global__ void __launch_bounds__(64) transpose_w(const float* __restrict__ wsrc) {
    int m = blockIdx.x;   // 0..95
    int o = threadIdx.x;  // 0..63
    const float2* src = (const float2*)wsrc;
    float2* dst = (float2*)d_wT;
    #pragma unroll 4
    for (int i = 0; i < CI; ++i) {
        dst[(m*CI + i)*CO + o] = src[(size_t)(i*CO + o)*96 + m];
    }
}

// ---------- K1: forward row DFT (folded) + fused partial column DFT ----------
// smem layout (floats): sx[64*260] | stw[128*28] | shc2[512] | shs2[512] | sT[64*25]
__global__ void __launch_bounds__(256) k1_fwd(const float* __restrict__ x) {
    extern __shared__ float sm[];
    float* sx   = sm;             // 16640
    float* stw  = sm + 16640;     // 3584
    float* shc2 = sm + 20224;     // 512
    float* shs2 = sm + 20736;     // 512
    float* sT   = sm + 21248;     // 1600

    int bc = blockIdx.y;
    int hb = blockIdx.x;          // 0..3  (also the partial-part index)
    int h0 = hb * 64;
    int t  = threadIdx.x;

    for (int i = t; i < 128*28; i += 256) stw[i] = d_twp[i];
    for (int i = t; i < 512; i += 256) {
        int kx = i >> 6, r = i & 63;
        shc2[i] = d_hc[kx*256 + h0 + r];
        shs2[i] = d_hs[kx*256 + h0 + r];
    }
    const float* xb = x + ((size_t)bc*H + h0)*W;
    for (int i = t; i < 4096; i += 256) {
        int r = i >> 6, wq = i & 63;
        float4 v = ((const float4*)(xb + (size_t)r*W))[wq];
        *((float4*)(sx + r*260 + wq*4)) = v;
    }
    __syncthreads();

    int rp = t >> 3;        // 0..31 row pair
    int qc = t & 7;         // 0..7 w-phase
    int r0 = rp*2, r1 = r0 + 1;

    // acc layout per row: [0..5] CE, [6..11] SE(imag even), [12..17] CO, [18..23] SO(imag odd)
    float a0[24], a1[24];
    #pragma unroll
    for (int k = 0; k < 24; ++k) { a0[k] = 0.f; a1[k] = 0.f; }

    const float* px0 = sx + r0*260;
    const float* px1 = sx + r1*260;

    #pragma unroll 2
    for (int j = 0; j < 16; ++j) {
        int w = qc + 8*j;      // 0..127
        float xa0 = px0[w], xb0 = px0[w + 128];
        float xa1 = px1[w], xb1 = px1[w + 128];
        float S0_ = xa0 + xb0, D0_ = xa0 - xb0;
        float S1_ = xa1 + xb1, D1_ = xa1 - xb1;

        float tw[24];
        const float4* tp = (const float4*)(stw + w*28);
        float4 f0 = tp[0], f1 = tp[1], f2 = tp[2], f3 = tp[3], f4 = tp[4], f5 = tp[5];
        tw[0]=f0.x; tw[1]=f0.y; tw[2]=f0.z; tw[3]=f0.w;
        tw[4]=f1.x; tw[5]=f1.y; tw[6]=f1.z; tw[7]=f1.w;
        tw[8]=f2.x; tw[9]=f2.y; tw[10]=f2.z; tw[11]=f2.w;
        tw[12]=f3.x; tw[13]=f3.y; tw[14]=f3.z; tw[15]=f3.w;
        tw[16]=f4.x; tw[17]=f4.y; tw[18]=f4.z; tw[19]=f4.w;
        tw[20]=f5.x; tw[21]=f5.y; tw[22]=f5.z; tw[23]=f5.w;

        #pragma unroll
        for (int k = 0; k < 12; ++k) {
            a0[k]    += S0_ * tw[k];
            a0[12+k] += D0_ * tw[12+k];
            a1[k]    += S1_ * tw[k];
            a1[12+k] += D1_ * tw[12+k];
        }
    }

    // reduce across qc (lane bits 0..2)
    #pragma unroll
    for (int k = 0; k < 24; ++k) {
        float v;
        v = a0[k]; v += __shfl_xor_sync(0xffffffffu, v, 1); v += __shfl_xor_sync(0xffffffffu, v, 2); v += __shfl_xor_sync(0xffffffffu, v, 4); a0[k] = v;
        v = a1[k]; v += __shfl_xor_sync(0xffffffffu, v, 1); v += __shfl_xor_sync(0xffffffffu, v, 2); v += __shfl_xor_sync(0xffffffffu, v, 4); a1[k] = v;
    }

    if (qc == 0) {
        // tables pre-scaled: acc values are already T (re in CE/CO slots, im in SE/SO)
        float* T0 = sT + r0*25;
        float* T1 = sT + r1*25;
        #pragma unroll
        for (int m = 0; m < 6; ++m) {
            T0[2*m]        = a0[m];       // re, even ky
            T0[12 + 2*m]   = a0[6+m];     // im, even ky
            T0[2*m+1]      = a0[12+m];    // re, odd ky
            T0[12 + 2*m+1] = a0[18+m];    // im, odd ky
            T1[2*m]        = a1[m];
            T1[12 + 2*m]   = a1[6+m];
            T1[2*m+1]      = a1[12+m];
            T1[12 + 2*m+1] = a1[18+m];
        }
    }
    __syncthreads();

    // fused partial column DFT over this block's 64 rows
    if (t < 96) {
        int kx = t / 12, ky = t % 12;
        float xr = 0.f, xi = 0.f;
        #pragma unroll 4
        for (int r = 0; r < 64; ++r) {
            float tre = sT[r*25 + ky];
            float tim = sT[r*25 + 12 + ky];
            float c = shc2[kx*64 + r];
            float s = shs2[kx*64 + r];
            xr += tre*c + tim*s;
            xi += tim*c - tre*s;
        }
        int b = bc >> 6, ci = bc & 63;
        ((float2*)d_Xp)[((size_t)(b*96 + t)*CI + ci)*4 + hb] = make_float2(xr, xi);
    }
}

// ---------- K3: per-mode channel mixing (sums the 4 partials) ----------
__global__ void __launch_bounds__(64) k3_mix() {
    __shared__ float2 sXm[CI];
    int m = blockIdx.x;   // 0..95
    int b = blockIdx.y;   // 0..15
    int o = threadIdx.x;  // 0..63

    const float2* Xp = (const float2*)d_Xp + ((size_t)(b*96 + m)*CI + o)*4;
    float2 p0 = Xp[0], p1 = Xp[1], p2 = Xp[2], p3 = Xp[3];
    sXm[o] = make_float2(p0.x + p1.x + p2.x + p3.x, p0.y + p1.y + p2.y + p3.y);
    __syncthreads();

    float yr = 0.f, yi = 0.f;
    const float2* wp = (const float2*)d_wT + (size_t)m*CI*CO + o;
    #pragma unroll 8
    for (int i = 0; i < CI; ++i) {
        float2 xv = sXm[i];
        float2 wv = wp[(size_t)i*CO];
        yr += xv.x*wv.x - xv.y*wv.y;
        yi += xv.x*wv.y + xv.y*wv.x;
    }
    ((float2*)d_Y)[(size_t)(b*CO + o)*96 + m] = make_float2(yr, yi);
}

// ---------- K45: inverse column ifft (coeffs) + folded inverse row synthesis ----------
__global__ void __launch_bounds__(256) k45_inv(float* __restrict__ out) {
    __shared__ float sY[192];
    __shared__ float shc[MH*260];
    __shared__ float shs[MH*260];
    __shared__ __align__(16) float sC[256*28];  // [h][a0..a11, b0..b11] pad 28

    int bo = blockIdx.x;     // b*CO + o
    int t  = threadIdx.x;

    for (int i = t; i < 192;   i += 256) sY[i] = d_Y[(size_t)bo*192 + i];
    for (int i = t; i < MH*H;  i += 256) {
        int kx = i >> 8, h = i & 255;
        shc[kx*260 + h] = d_hc[i];
        shs[kx*260 + h] = d_hs[i];
    }
    int wv = t & 127;
    float cr[12], sr[12];
    #pragma unroll
    for (int ky = 0; ky < 12; ++ky) {
        cr[ky] = d_ctab[ky*256 + wv];
        sr[ky] = d_stab[ky*256 + wv];
    }
    __syncthreads();

    // coefficients for h = t
    {
        float gre[12], gim[12];
        #pragma unroll
        for (int ky = 0; ky < 12; ++ky) { gre[ky]=0.f; gim[ky]=0.f; }
        #pragma unroll
        for (int kx = 0; kx < MH; ++kx) {
            float c = shc[kx*260 + t];
            float s = shs[kx*260 + t];
            #pragma unroll
            for (int ky = 0; ky < 12; ++ky) {
                float yr = sY[(kx*12 + ky)*2];
                float yi = sY[(kx*12 + ky)*2 + 1];
                gre[ky] += yr*c - yi*s;
                gim[ky] += yr*s + yi*c;
            }
        }
        sC[t*28 + 0] = S2*gre[0];
        #pragma unroll
        for (int ky = 1; ky < 12; ++ky) sC[t*28 + ky] = 2.f*S2*gre[ky];
        #pragma unroll
        for (int ky = 0; ky < 12; ++ky) sC[t*28 + 12 + ky] = -2.f*S2*gim[ky];
    }
    __syncthreads();

    // folded synthesis: thread handles w pair (wv, wv+128) over 128 rows
    int hbase = (t >> 7) * 128;
    float* op = out + (size_t)bo*H*W;
    #pragma unroll 2
    for (int hh = 0; hh < 128; ++hh) {
        int h = hbase + hh;
        const float4* p = (const float4*)(sC + h*28);
        float4 a0 = p[0], a1 = p[1], a2 = p[2];
        float4 b0 = p[3], b1 = p[4], b2 = p[5];
        float E, O;
        E  = a0.x*cr[0]  + a0.z*cr[2]  + a1.x*cr[4]  + a1.z*cr[6]  + a2.x*cr[8]  + a2.z*cr[10];
        E += b0.x*sr[0]  + b0.z*sr[2]  + b1.x*sr[4]  + b1.z*sr[6]  + b2.x*sr[8]  + b2.z*sr[10];
        O  = a0.y*cr[1]  + a0.w*cr[3]  + a1.y*cr[5]  + a1.w*cr[7]  + a2.y*cr[9]  + a2.w*cr[11];
        O += b0.y*sr[1]  + b0.w*sr[3]  + b1.y*sr[5]  + b1.w*sr[7]  + b2.y*sr[9]  + b2.w*sr[11];
        op[(size_t)h*W + wv]       = E + O;
        op[(size_t)h*W + wv + 128] = E - O;
    }
}

// ---------- launch ----------
extern "C" void kernel_launch(void* const* d_in, const int* in_sizes, int n_in,
                              void* d_out, int out_size) {
    const float* x = (const float*)d_in[0];
    const float* w = (const float*)d_in[1];
    float* out = (float*)d_out;

    cudaFuncSetAttribute(k1_fwd, cudaFuncAttributeMaxDynamicSharedMemorySize, 91392);

    init_trig<<<33, 256>>>();
    transpose_w<<<96, 64>>>(w);
    k1_fwd<<<dim3(4, B*CI), 256, 91392>>>(x);
    k3_mix<<<dim3(96, B), 64>>>();
    k45_inv<<<B*CO, 256>>>(out);
}

// round 4
// speedup vs baseline: 1.5227x; 1.5227x over previous
#include <cuda_runtime.h>
#include <math.h>

#define B   16
#define CI  64
#define CO  64
#define H   256
#define W   256
#define MH  8
#define MW  12
#define NPART 8
#define S1  (1.0f/256.0f)
#define S2  (1.0f/256.0f)

// ---------- device scratch ----------
__device__ float d_ctab[MW*W];           // cos(2*pi*ky*w/256)
__device__ float d_stab[MW*W];           // sin(2*pi*ky*w/256)
__device__ float d_hc[MH*H];             // cos(2*pi*kx*h/256)
__device__ float d_hs[MH*H];             // sin(2*pi*kx*h/256)
__device__ float d_twp[128*28];          // packed folded twiddles (pre-scaled S1, sin negated)
__device__ float d_Xp[(size_t)B*96*CI*NPART*2];  // per-block partial X
__device__ float d_Y[(size_t)B*CO*96*2];
__device__ float d_wT[(size_t)96*CI*CO*2];

// ---------- trig tables ----------
__global__ void init_trig() {
    int idx = blockIdx.x * blockDim.x + threadIdx.x;
    if (idx < 3072) {
        int ky = idx >> 8, w = idx & 255;
        double a = 2.0 * (double)ky * (double)w / 256.0;
        double s, c; sincospi(a, &s, &c);
        d_ctab[idx] = (float)c; d_stab[idx] = (float)s;
    } else if (idx < 5120) {
        int j = idx - 3072;
        int kx = j >> 8, h = j & 255;
        double a = 2.0 * (double)kx * (double)h / 256.0;
        double s, c; sincospi(a, &s, &c);
        d_hc[j] = (float)c; d_hs[j] = (float)s;
    } else if (idx < 5120 + 128*24) {
        int j = idx - 5120;
        int w = j / 24, k = j % 24;
        int m = k % 6;
        int ky = (k < 12) ? 2*m : 2*m + 1;
        double a = 2.0 * (double)ky * (double)w / 256.0;
        double s, c; sincospi(a, &s, &c);
        bool is_sin = ((k >= 6 && k < 12) || k >= 18);
        d_twp[w*28 + k] = is_sin ? (float)(-S1 * s) : (float)(S1 * c);
    }
}

// ---------- weight transpose ----------
__global__ void __launch_bounds__(64) transpose_w(const float* __restrict__ wsrc) {
    int m = blockIdx.x;
    int o = threadIdx.x;
    const float2* src = (const float2*)wsrc;
    float2* dst = (float2*)d_wT;
    #pragma unroll 4
    for (int i = 0; i < CI; ++i) {
        dst[(m*CI + i)*CO + o] = src[(size_t)(i*CO + o)*96 + m];
    }
}

// ---------- filler so k1 lands at ncu capture slot 4 ----------
__global__ void k_filler() {}

// ---------- K1 v3: 32 rows/block, 1 row/thread, 8 qc phases ----------
// smem: sx[32*260] | stw[128*28] | shc2[256] | shs2[256] | sT[32*25]
__global__ void __launch_bounds__(256) k1_fwd(const float* __restrict__ x) {
    extern __shared__ float sm[];
    float* sx   = sm;              // 8320 floats
    float* stw  = sm + 8320;       // 3584
    float* shc2 = sm + 11904;      // 256  (8 kx x 32 rows)
    float* shs2 = sm + 12160;      // 256
    float* sT   = sm + 12416;      // 800
    // total 13216 floats = 52864 B

    int bc = blockIdx.y;
    int hb = blockIdx.x;          // 0..7 partial index
    int h0 = hb * 32;
    int t  = threadIdx.x;

    for (int i = t; i < 128*28; i += 256) stw[i] = d_twp[i];
    if (t < 256) {
        int kx = t >> 5, r = t & 31;
        shc2[t] = d_hc[kx*256 + h0 + r];
        shs2[t] = d_hs[kx*256 + h0 + r];
    }
    const float* xb = x + ((size_t)bc*H + h0)*W;
    for (int i = t; i < 2048; i += 256) {
        int r = i >> 6, wq = i & 63;
        float4 v = ((const float4*)(xb + (size_t)r*W))[wq];
        *((float4*)(sx + r*260 + wq*4)) = v;
    }
    __syncthreads();

    int r  = t >> 3;        // 0..31 row
    int qc = t & 7;         // 0..7 w-phase

    // acc: [0..5] re even ky, [6..11] im even, [12..17] re odd, [18..23] im odd
    float a0[24];
    #pragma unroll
    for (int k = 0; k < 24; ++k) a0[k] = 0.f;

    const float* px = sx + r*260;

    #pragma unroll 4
    for (int j = 0; j < 16; ++j) {
        int w = qc + 8*j;
        float xa = px[w], xb2 = px[w + 128];
        float Sv = xa + xb2, Dv = xa - xb2;

        const float4* tp = (const float4*)(stw + w*28);
        float4 f0 = tp[0], f1 = tp[1], f2 = tp[2];
        float4 f3 = tp[3], f4 = tp[4], f5 = tp[5];

        a0[0]  += Sv*f0.x; a0[1]  += Sv*f0.y; a0[2]  += Sv*f0.z; a0[3]  += Sv*f0.w;
        a0[4]  += Sv*f1.x; a0[5]  += Sv*f1.y; a0[6]  += Sv*f1.z; a0[7]  += Sv*f1.w;
        a0[8]  += Sv*f2.x; a0[9]  += Sv*f2.y; a0[10] += Sv*f2.z; a0[11] += Sv*f2.w;
        a0[12] += Dv*f3.x; a0[13] += Dv*f3.y; a0[14] += Dv*f3.z; a0[15] += Dv*f3.w;
        a0[16] += Dv*f4.x; a0[17] += Dv*f4.y; a0[18] += Dv*f4.z; a0[19] += Dv*f4.w;
        a0[20] += Dv*f5.x; a0[21] += Dv*f5.y; a0[22] += Dv*f5.z; a0[23] += Dv*f5.w;
    }

    #pragma unroll
    for (int k = 0; k < 24; ++k) {
        float v = a0[k];
        v += __shfl_xor_sync(0xffffffffu, v, 1);
        v += __shfl_xor_sync(0xffffffffu, v, 2);
        v += __shfl_xor_sync(0xffffffffu, v, 4);
        a0[k] = v;
    }

    if (qc == 0) {
        float* T0 = sT + r*25;
        #pragma unroll
        for (int m = 0; m < 6; ++m) {
            T0[2*m]        = a0[m];       // re, even ky
            T0[12 + 2*m]   = a0[6+m];     // im, even ky
            T0[2*m+1]      = a0[12+m];    // re, odd ky
            T0[12 + 2*m+1] = a0[18+m];    // im, odd ky
        }
    }
    __syncthreads();

    // fused partial column DFT over this block's 32 rows
    if (t < 96) {
        int kx = t / 12, ky = t % 12;
        float xr = 0.f, xi = 0.f;
        #pragma unroll
        for (int rr = 0; rr < 32; ++rr) {
            float tre = sT[rr*25 + ky];
            float tim = sT[rr*25 + 12 + ky];
            float c = shc2[kx*32 + rr];
            float s = shs2[kx*32 + rr];
            xr += tre*c + tim*s;
            xi += tim*c - tre*s;
        }
        int b = bc >> 6, ci = bc & 63;
        ((float2*)d_Xp)[((size_t)(b*96 + t)*CI + ci)*NPART + hb] = make_float2(xr, xi);
    }
}

// ---------- K3: mode mixing (sums NPART partials) ----------
__global__ void __launch_bounds__(64) k3_mix() {
    __shared__ float2 sXm[CI];
    int m = blockIdx.x;
    int b = blockIdx.y;
    int o = threadIdx.x;

    const float2* Xp = (const float2*)d_Xp + ((size_t)(b*96 + m)*CI + o)*NPART;
    float xr = 0.f, xi = 0.f;
    #pragma unroll
    for (int p = 0; p < NPART; ++p) { float2 v = Xp[p]; xr += v.x; xi += v.y; }
    sXm[o] = make_float2(xr, xi);
    __syncthreads();

    float yr = 0.f, yi = 0.f;
    const float2* wp = (const float2*)d_wT + (size_t)m*CI*CO + o;
    #pragma unroll 8
    for (int i = 0; i < CI; ++i) {
        float2 xv = sXm[i];
        float2 wv = wp[(size_t)i*CO];
        yr += xv.x*wv.x - xv.y*wv.y;
        yi += xv.x*wv.y + xv.y*wv.x;
    }
    ((float2*)d_Y)[(size_t)(b*CO + o)*96 + m] = make_float2(yr, yi);
}

// ---------- K45: inverse column ifft + folded row synthesis ----------
__global__ void __launch_bounds__(256) k45_inv(float* __restrict__ out) {
    __shared__ float sY[192];
    __shared__ float shc[MH*260];
    __shared__ float shs[MH*260];
    __shared__ __align__(16) float sC[256*28];

    int bo = blockIdx.x;
    int t  = threadIdx.x;

    for (int i = t; i < 192;   i += 256) sY[i] = d_Y[(size_t)bo*192 + i];
    for (int i = t; i < MH*H;  i += 256) {
        int kx = i >> 8, h = i & 255;
        shc[kx*260 + h] = d_hc[i];
        shs[kx*260 + h] = d_hs[i];
    }
    int wv = t & 127;
    float cr[12], sr[12];
    #pragma unroll
    for (int ky = 0; ky < 12; ++ky) {
        cr[ky] = d_ctab[ky*256 + wv];
        sr[ky] = d_stab[ky*256 + wv];
    }
    __syncthreads();

    {
        float gre[12], gim[12];
        #pragma unroll
        for (int ky = 0; ky < 12; ++ky) { gre[ky]=0.f; gim[ky]=0.f; }
        #pragma unroll
        for (int kx = 0; kx < MH; ++kx) {
            float c = shc[kx*260 + t];
            float s = shs[kx*260 + t];
            #pragma unroll
            for (int ky = 0; ky < 12; ++ky) {
                float yr = sY[(kx*12 + ky)*2];
                float yi = sY[(kx*12 + ky)*2 + 1];
                gre[ky] += yr*c - yi*s;
                gim[ky] += yr*s + yi*c;
            }
        }
        sC[t*28 + 0] = S2*gre[0];
        #pragma unroll
        for (int ky = 1; ky < 12; ++ky) sC[t*28 + ky] = 2.f*S2*gre[ky];
        #pragma unroll
        for (int ky = 0; ky < 12; ++ky) sC[t*28 + 12 + ky] = -2.f*S2*gim[ky];
    }
    __syncthreads();

    int hbase = (t >> 7) * 128;
    float* op = out + (size_t)bo*H*W;
    #pragma unroll 2
    for (int hh = 0; hh < 128; ++hh) {
        int h = hbase + hh;
        const float4* p = (const float4*)(sC + h*28);
        float4 a0 = p[0], a1 = p[1], a2 = p[2];
        float4 b0 = p[3], b1 = p[4], b2 = p[5];
        float E, O;
        E  = a0.x*cr[0]  + a0.z*cr[2]  + a1.x*cr[4]  + a1.z*cr[6]  + a2.x*cr[8]  + a2.z*cr[10];
        E += b0.x*sr[0]  + b0.z*sr[2]  + b1.x*sr[4]  + b1.z*sr[6]  + b2.x*sr[8]  + b2.z*sr[10];
        O  = a0.y*cr[1]  + a0.w*cr[3]  + a1.y*cr[5]  + a1.w*cr[7]  + a2.y*cr[9]  + a2.w*cr[11];
        O += b0.y*sr[1]  + b0.w*sr[3]  + b1.y*sr[5]  + b1.w*sr[7]  + b2.y*sr[9]  + b2.w*sr[11];
        op[(size_t)h*W + wv]       = E + O;
        op[(size_t)h*W + wv + 128] = E - O;
    }
}

// ---------- launch ----------
extern "C" void kernel_launch(void* const* d_in, const int* in_sizes, int n_in,
                              void* d_out, int out_size) {
    const float* x = (const float*)d_in[0];
    const float* w = (const float*)d_in[1];
    float* out = (float*)d_out;

    cudaFuncSetAttribute(k1_fwd, cudaFuncAttributeMaxDynamicSharedMemorySize, 52864);

    init_trig<<<33, 256>>>();      // launch 1
    transpose_w<<<96, 64>>>(w);    // launch 2
    k_filler<<<1, 32>>>();         // launch 3
    k1_fwd<<<dim3(8, B*CI), 256, 52864>>>(x);   // launch 4  <-- ncu capture slot
    k3_mix<<<dim3(96, B), 64>>>(); // launch 5
    k45_inv<<<B*CO, 256>>>(out);   // launch 6
}

// round 5
// speedup vs baseline: 2.1621x; 1.4199x over previous
#include <cuda_runtime.h>
#include <math.h>

#define B   16
#define CI  64
#define CO  64
#define H   256
#define W   256
#define MH  8
#define MW  12
#define NPART 4
#define S1  (1.0f/256.0f)
#define S2  (1.0f/256.0f)

// ---------- device scratch ----------
__device__ float d_ctab[MW*W];           // cos(2*pi*ky*w/256)
__device__ float d_stab[MW*W];           // sin
__device__ float d_hc[MH*H];             // cos(2*pi*kx*h/256)
__device__ float d_hs[MH*H];
__device__ float d_tw2[24*128];          // folded fwd twiddles [slot][w], pre-scaled S1, sin negated
__device__ float d_Xp[(size_t)B*96*CI*NPART*2];
__device__ float d_Y[(size_t)B*CO*96*2];
__device__ float d_wT[(size_t)96*CI*CO*2];

// ---------- merged init: trig tables + weight transpose ----------
__global__ void __launch_bounds__(256) init_all(const float* __restrict__ wsrc) {
    int bx = blockIdx.x;
    int t  = threadIdx.x;
    if (bx < 32) {
        int idx = bx*256 + t;
        if (idx < 3072) {                       // k45 synthesis tables
            int ky = idx >> 8, w = idx & 255;
            double a = 2.0 * (double)ky * (double)w / 256.0;
            double s, c; sincospi(a, &s, &c);
            d_ctab[idx] = (float)c; d_stab[idx] = (float)s;
        } else if (idx < 5120) {                // column DFT tables
            int j = idx - 3072;
            int kx = j >> 8, h = j & 255;
            double a = 2.0 * (double)kx * (double)h / 256.0;
            double s, c; sincospi(a, &s, &c);
            d_hc[j] = (float)c; d_hs[j] = (float)s;
        } else if (idx < 8192) {                // folded fwd twiddles [slot][w]
            int j = idx - 5120;
            int s_ = j >> 7, w = j & 127;
            int ky; bool is_sin;
            if      (s_ <  6) { ky = 2*s_;          is_sin = false; }
            else if (s_ < 12) { ky = 2*(s_-6);      is_sin = true;  }
            else if (s_ < 18) { ky = 2*(s_-12)+1;   is_sin = false; }
            else              { ky = 2*(s_-18)+1;   is_sin = true;  }
            double a = 2.0 * (double)ky * (double)w / 256.0;
            double sv, cv; sincospi(a, &sv, &cv);
            d_tw2[j] = is_sin ? (float)(-S1 * sv) : (float)(S1 * cv);
        }
    } else {                                    // weight transpose: [i][o][m] -> [m][i][o]
        int m = bx - 32;                        // 0..95
        if (m < 96) {
            int o = t & 63;
            const float2* src = (const float2*)wsrc;
            float2* dst = (float2*)d_wT;
            #pragma unroll
            for (int i = (t >> 6); i < CI; i += 4) {
                dst[(m*CI + i)*CO + o] = src[(size_t)(i*CO + o)*96 + m];
            }
        }
    }
}

// ---------- K1 v4: 64 rows/block, register tile 4 rows x 6 modes ----------
// smem floats: sS[64*132] sD[64*132] stw[24*132] sT[64*25] shc2[512] shs2[512]
__global__ void __launch_bounds__(256) k1_fwd(const float* __restrict__ x) {
    extern __shared__ float sm[];
    float* sS   = sm;              // 8448
    float* sD   = sm + 8448;       // 8448
    float* stw  = sm + 16896;      // 3168
    float* sT   = sm + 20064;      // 1600
    float* shc2 = sm + 21664;      // 512
    float* shs2 = sm + 22176;      // 512  -> total 22688 floats = 90752 B

    int bc = blockIdx.y;
    int hb = blockIdx.x;          // 0..3 partial index
    int h0 = hb * 64;
    int t  = threadIdx.x;

    for (int i = t; i < 24*128; i += 256) {
        int k = i >> 7, w = i & 127;
        stw[k*132 + w] = d_tw2[i];
    }
    for (int i = t; i < 512; i += 256) {
        int kx = i >> 6, r = i & 63;
        shc2[i] = d_hc[kx*256 + h0 + r];
        shs2[i] = d_hs[kx*256 + h0 + r];
    }
    const float* xb = x + ((size_t)bc*H + h0)*W;
    #pragma unroll
    for (int i = t; i < 2048; i += 256) {
        int r = i >> 5, wq = i & 31;
        const float4* rp = (const float4*)(xb + (size_t)r*W);
        float4 va = rp[wq];
        float4 vb = rp[wq + 32];
        *((float4*)(sS + r*132 + wq*4)) = make_float4(va.x+vb.x, va.y+vb.y, va.z+vb.z, va.w+vb.w);
        *((float4*)(sD + r*132 + wq*4)) = make_float4(va.x-vb.x, va.y-vb.y, va.z-vb.z, va.w-vb.w);
    }
    __syncthreads();

    int qc = t & 3;          // 0..3 w-phase
    int kt = (t >> 2) & 3;   // 0..3 mode-tile (6 slots each)
    int rt = t >> 4;         // 0..15 row-tile (4 rows each)

    const float* xp = ((kt < 2) ? sS : sD) + rt*4*132;
    const float* tp = stw + kt*6*132;

    float acc[24];
    #pragma unroll
    for (int k = 0; k < 24; ++k) acc[k] = 0.f;

    #pragma unroll 4
    for (int j = 0; j < 32; ++j) {
        int w = qc + 4*j;
        float xv0 = xp[w], xv1 = xp[132+w], xv2 = xp[264+w], xv3 = xp[396+w];
        float t0 = tp[w],     t1 = tp[132+w], t2 = tp[264+w];
        float t3 = tp[396+w], t4 = tp[528+w], t5 = tp[660+w];

        acc[0]  += xv0*t0; acc[1]  += xv0*t1; acc[2]  += xv0*t2;
        acc[3]  += xv0*t3; acc[4]  += xv0*t4; acc[5]  += xv0*t5;
        acc[6]  += xv1*t0; acc[7]  += xv1*t1; acc[8]  += xv1*t2;
        acc[9]  += xv1*t3; acc[10] += xv1*t4; acc[11] += xv1*t5;
        acc[12] += xv2*t0; acc[13] += xv2*t1; acc[14] += xv2*t2;
        acc[15] += xv2*t3; acc[16] += xv2*t4; acc[17] += xv2*t5;
        acc[18] += xv3*t0; acc[19] += xv3*t1; acc[20] += xv3*t2;
        acc[21] += xv3*t3; acc[22] += xv3*t4; acc[23] += xv3*t5;
    }

    // reduce across qc (lane bits 0..1)
    #pragma unroll
    for (int k = 0; k < 24; ++k) {
        float v = acc[k];
        v += __shfl_xor_sync(0xffffffffu, v, 1);
        v += __shfl_xor_sync(0xffffffffu, v, 2);
        acc[k] = v;
    }

    if (qc == 0) {
        #pragma unroll
        for (int rr = 0; rr < 4; ++rr) {
            float* Trow = sT + (rt*4 + rr)*25 + kt*6;
            #pragma unroll
            for (int s = 0; s < 6; ++s) Trow[s] = acc[rr*6 + s];
        }
    }
    __syncthreads();

    // fused partial column DFT over this block's 64 rows
    // sT slots: 0..5 re(ky=2m), 6..11 im(ky=2m), 12..17 re(ky=2m+1), 18..23 im(ky=2m+1)
    if (t < 96) {
        int kx = t / 12, ky = t % 12;
        int res = (ky & 1) ? 12 + (ky >> 1) : (ky >> 1);
        int ims = res + 6;
        float xr = 0.f, xi = 0.f;
        #pragma unroll 4
        for (int rr = 0; rr < 64; ++rr) {
            float tre = sT[rr*25 + res];
            float tim = sT[rr*25 + ims];
            float c = shc2[kx*64 + rr];
            float s = shs2[kx*64 + rr];
            xr += tre*c + tim*s;
            xi += tim*c - tre*s;
        }
        int b = bc >> 6, ci = bc & 63;
        ((float2*)d_Xp)[((size_t)(b*96 + t)*CI + ci)*NPART + hb] = make_float2(xr, xi);
    }
}

// ---------- K3: mode mixing (4 modes per block) ----------
__global__ void __launch_bounds__(256) k3_mix() {
    __shared__ float2 sXm[4][CI];
    int m0 = blockIdx.x * 4;   // 0..92
    int b  = blockIdx.y;
    int ms = threadIdx.x >> 6; // 0..3
    int o  = threadIdx.x & 63;
    int m  = m0 + ms;

    const float2* Xp = (const float2*)d_Xp + ((size_t)(b*96 + m)*CI + o)*NPART;
    float xr = 0.f, xi = 0.f;
    #pragma unroll
    for (int p = 0; p < NPART; ++p) { float2 v = Xp[p]; xr += v.x; xi += v.y; }
    sXm[ms][o] = make_float2(xr, xi);
    __syncthreads();

    float yr = 0.f, yi = 0.f;
    const float2* wp = (const float2*)d_wT + (size_t)m*CI*CO + o;
    #pragma unroll 8
    for (int i = 0; i < CI; ++i) {
        float2 xv = sXm[ms][i];
        float2 wv = wp[(size_t)i*CO];
        yr += xv.x*wv.x - xv.y*wv.y;
        yi += xv.x*wv.y + xv.y*wv.x;
    }
    ((float2*)d_Y)[(size_t)(b*CO + o)*96 + m] = make_float2(yr, yi);
}

// ---------- K45: inverse column ifft + folded row synthesis ----------
__global__ void __launch_bounds__(256) k45_inv(float* __restrict__ out) {
    __shared__ float sY[192];
    __shared__ float shc[MH*260];
    __shared__ float shs[MH*260];
    __shared__ __align__(16) float sC[256*28];

    int bo = blockIdx.x;
    int t  = threadIdx.x;

    for (int i = t; i < 192;   i += 256) sY[i] = d_Y[(size_t)bo*192 + i];
    for (int i = t; i < MH*H;  i += 256) {
        int kx = i >> 8, h = i & 255;
        shc[kx*260 + h] = d_hc[i];
        shs[kx*260 + h] = d_hs[i];
    }
    int wv = t & 127;
    float cr[12], sr[12];
    #pragma unroll
    for (int ky = 0; ky < 12; ++ky) {
        cr[ky] = d_ctab[ky*256 + wv];
        sr[ky] = d_stab[ky*256 + wv];
    }
    __syncthreads();

    {
        float gre[12], gim[12];
        #pragma unroll
        for (int ky = 0; ky < 12; ++ky) { gre[ky]=0.f; gim[ky]=0.f; }
        #pragma unroll
        for (int kx = 0; kx < MH; ++kx) {
            float c = shc[kx*260 + t];
            float s = shs[kx*260 + t];
            #pragma unroll
            for (int ky = 0; ky < 12; ++ky) {
                float yr = sY[(kx*12 + ky)*2];
                float yi = sY[(kx*12 + ky)*2 + 1];
                gre[ky] += yr*c - yi*s;
                gim[ky] += yr*s + yi*c;
            }
        }
        sC[t*28 + 0] = S2*gre[0];
        #pragma unroll
        for (int ky = 1; ky < 12; ++ky) sC[t*28 + ky] = 2.f*S2*gre[ky];
        #pragma unroll
        for (int ky = 0; ky < 12; ++ky) sC[t*28 + 12 + ky] = -2.f*S2*gim[ky];
    }
    __syncthreads();

    int hbase = (t >> 7) * 128;
    float* op = out + (size_t)bo*H*W;
    #pragma unroll 4
    for (int hh = 0; hh < 128; ++hh) {
        int h = hbase + hh;
        const float4* p = (const float4*)(sC + h*28);
        float4 a0 = p[0], a1 = p[1], a2 = p[2];
        float4 b0 = p[3], b1 = p[4], b2 = p[5];
        float E, O;
        E  = a0.x*cr[0]  + a0.z*cr[2]  + a1.x*cr[4]  + a1.z*cr[6]  + a2.x*cr[8]  + a2.z*cr[10];
        E += b0.x*sr[0]  + b0.z*sr[2]  + b1.x*sr[4]  + b1.z*sr[6]  + b2.x*sr[8]  + b2.z*sr[10];
        O  = a0.y*cr[1]  + a0.w*cr[3]  + a1.y*cr[5]  + a1.w*cr[7]  + a2.y*cr[9]  + a2.w*cr[11];
        O += b0.y*sr[1]  + b0.w*sr[3]  + b1.y*sr[5]  + b1.w*sr[7]  + b2.y*sr[9]  + b2.w*sr[11];
        op[(size_t)h*W + wv]       = E + O;
        op[(size_t)h*W + wv + 128] = E - O;
    }
}

// ---------- launch ----------
extern "C" void kernel_launch(void* const* d_in, const int* in_sizes, int n_in,
                              void* d_out, int out_size) {
    const float* x = (const float*)d_in[0];
    const float* w = (const float*)d_in[1];
    float* out = (float*)d_out;

    cudaFuncSetAttribute(k1_fwd, cudaFuncAttributeMaxDynamicSharedMemorySize, 90752);

    init_all<<<128, 256>>>(w);                   // launch 1
    k1_fwd<<<dim3(NPART, B*CI), 256, 90752>>>(x); // launch 2
    k3_mix<<<dim3(24, B), 256>>>();              // launch 3
    k45_inv<<<B*CO, 256>>>(out);                 // launch 4  <-- ncu capture slot
}